// round 4
// baseline (speedup 1.0000x reference)
#include <cuda_runtime.h>

// g[b,0,i,j] = cos(phi_i + phi_j) with phi = arccos(c)
//            = c_i*c_j - s_i*s_j,  s = sqrt(1 - c^2)
// c = clamp((2x - mx - mn)/(mx - mn), -1+eps, 1-eps) per batch row.
//
// Two-phase: k1 computes (c,s) per element into L2-resident scratch (2 MB),
// k2 is a barrier-free pure store streamer.

#define N 512
#define B 512
#define THREADS 256
#define CHUNKS 8                      // row-chunks per batch in k2
#define ROWS_PER_CHUNK (N / CHUNKS)   // 64

// 512*512 (c,s) pairs = 2 MB scratch, stays in L2.
__device__ __align__(16) float2 g_cs[B * N];

__global__ __launch_bounds__(THREADS)
void gram_prep_kernel(const float* __restrict__ x) {
    const int b = blockIdx.x;
    const int tid = threadIdx.x;

    __shared__ float wmn[8], wmx[8];
    __shared__ float red_mn, red_mx;

    const float* __restrict__ xb = x + (size_t)b * N;
    float v0 = __ldg(xb + tid);
    float v1 = __ldg(xb + tid + THREADS);

    float mn = fminf(v0, v1);
    float mx = fmaxf(v0, v1);
    #pragma unroll
    for (int o = 16; o > 0; o >>= 1) {
        mn = fminf(mn, __shfl_xor_sync(0xFFFFFFFFu, mn, o));
        mx = fmaxf(mx, __shfl_xor_sync(0xFFFFFFFFu, mx, o));
    }
    if ((tid & 31) == 0) { wmn[tid >> 5] = mn; wmx[tid >> 5] = mx; }
    __syncthreads();
    if (tid < 32) {
        float m1 = (tid < 8) ? wmn[tid] : 3.0e38f;
        float m2 = (tid < 8) ? wmx[tid] : -3.0e38f;
        #pragma unroll
        for (int o = 4; o > 0; o >>= 1) {
            m1 = fminf(m1, __shfl_xor_sync(0xFFFFFFFFu, m1, o));
            m2 = fmaxf(m2, __shfl_xor_sync(0xFFFFFFFFu, m2, o));
        }
        if (tid == 0) { red_mn = m1; red_mx = m2; }
    }
    __syncthreads();

    const float lo = red_mn, hi = red_mx;
    const float inv = 1.0f / (hi - lo);
    const float shift = hi + lo;
    const float EPS = 1e-6f;

    float c0 = (2.0f * v0 - shift) * inv;
    c0 = fminf(fmaxf(c0, -1.0f + EPS), 1.0f - EPS);
    float c1 = (2.0f * v1 - shift) * inv;
    c1 = fminf(fmaxf(c1, -1.0f + EPS), 1.0f - EPS);
    float s0 = sqrtf(fmaxf(1.0f - c0 * c0, 0.0f));
    float s1 = sqrtf(fmaxf(1.0f - c1 * c1, 0.0f));

    float2* __restrict__ cs = g_cs + (size_t)b * N;
    cs[tid]           = make_float2(c0, s0);
    cs[tid + THREADS] = make_float2(c1, s1);
}

__global__ __launch_bounds__(THREADS)
void gram_store_kernel(float* __restrict__ out) {
    const int b = blockIdx.x;
    const int chunk = blockIdx.y;
    const int tid = threadIdx.x;

    const int row0 = chunk * ROWS_PER_CHUNK;
    const int col  = tid & 127;          // float4 column group 0..127
    const int half = tid >> 7;           // row parity

    const float2* __restrict__ cs = g_cs + (size_t)b * N;

    // Load this thread's 4 columns: two float4 = four (c,s) pairs
    const float4* __restrict__ cs4 = (const float4*)cs;
    const float4 p0 = __ldg(&cs4[2 * col]);
    const float4 p1 = __ldg(&cs4[2 * col + 1]);
    const float4 cj = make_float4(p0.x, p0.z, p1.x, p1.z);
    const float4 sj = make_float4(p0.y, p0.w, p1.y, p1.w);

    float4* __restrict__ out4 =
        (float4*)(out + (size_t)b * N * N + (size_t)row0 * N);

    // 64 rows, 2 halves -> 32 rows per thread
    #pragma unroll 8
    for (int r = half; r < ROWS_PER_CHUNK; r += 2) {
        const float2 cr = __ldg(&cs[row0 + r]);   // uniform -> broadcast, L1-hot
        const float ci = cr.x;
        const float si = cr.y;
        float4 rv;
        rv.x = fmaf(ci, cj.x, -si * sj.x);
        rv.y = fmaf(ci, cj.y, -si * sj.y);
        rv.z = fmaf(ci, cj.z, -si * sj.z);
        rv.w = fmaf(ci, cj.w, -si * sj.w);
        __stcs(&out4[r * 128 + col], rv);
    }
}

extern "C" void kernel_launch(void* const* d_in, const int* in_sizes, int n_in,
                              void* d_out, int out_size) {
    const float* x = (const float*)d_in[0];
    float* out = (float*)d_out;
    gram_prep_kernel<<<B, THREADS>>>(x);
    dim3 grid(B, CHUNKS);
    gram_store_kernel<<<grid, THREADS>>>(out);
}

// round 5
// speedup vs baseline: 1.0020x; 1.0020x over previous
#include <cuda_runtime.h>

// g[b,0,i,j] = cos(phi_i + phi_j) with phi = arccos(c)
//            = c_i*c_j - s_i*s_j,  s = sqrt(1 - c^2)
// c = clamp((2x - mx - mn)/(mx - mn), -1+eps, 1-eps) per batch row.
//
// Single kernel, zero barriers, zero smem: each warp redundantly
// min/max-reduces the batch row via shuffles, each thread derives its
// column (c,s) from registers and row (c,s) on the fly.

#define N 512
#define B 512
#define THREADS 256
#define CHUNKS 8                      // row-chunks per batch
#define ROWS_PER_CHUNK (N / CHUNKS)   // 64

__global__ __launch_bounds__(THREADS)
void gram_kernel(const float* __restrict__ x, float* __restrict__ out) {
    const int b = blockIdx.x;
    const int chunk = blockIdx.y;
    const int tid = threadIdx.x;
    const int lane = tid & 31;

    const float* __restrict__ xb = x + (size_t)b * N;
    const float4* __restrict__ xb4 = (const float4*)xb;

    // Warp-redundant min/max over all 512 floats: 4 lane-strided LDG.128.
    const float4 a0 = __ldg(&xb4[lane]);
    const float4 a1 = __ldg(&xb4[lane + 32]);
    const float4 a2 = __ldg(&xb4[lane + 64]);
    const float4 a3 = __ldg(&xb4[lane + 96]);

    float mn = fminf(fminf(fminf(a0.x, a0.y), fminf(a0.z, a0.w)),
                     fminf(fminf(a1.x, a1.y), fminf(a1.z, a1.w)));
    mn = fminf(mn, fminf(fminf(fminf(a2.x, a2.y), fminf(a2.z, a2.w)),
                         fminf(fminf(a3.x, a3.y), fminf(a3.z, a3.w))));
    float mx = fmaxf(fmaxf(fmaxf(a0.x, a0.y), fmaxf(a0.z, a0.w)),
                     fmaxf(fmaxf(a1.x, a1.y), fmaxf(a1.z, a1.w)));
    mx = fmaxf(mx, fmaxf(fmaxf(fmaxf(a2.x, a2.y), fmaxf(a2.z, a2.w)),
                         fmaxf(fmaxf(a3.x, a3.y), fmaxf(a3.z, a3.w))));
    #pragma unroll
    for (int o = 16; o > 0; o >>= 1) {
        mn = fminf(mn, __shfl_xor_sync(0xFFFFFFFFu, mn, o));
        mx = fmaxf(mx, __shfl_xor_sync(0xFFFFFFFFu, mx, o));
    }

    const float inv = 1.0f / (mx - mn);
    const float shift = mx + mn;
    const float EPS = 1e-6f;

    // This thread's 4 columns (re-read; L1-hot from the reduction loads)
    const int col  = tid & 127;          // float4 column group 0..127
    const int half = tid >> 7;           // row parity
    const float4 xc = __ldg(&xb4[col]);

    float4 cj, sj;
    cj.x = fminf(fmaxf(fmaf(2.0f, xc.x, -shift) * inv, -1.0f + EPS), 1.0f - EPS);
    cj.y = fminf(fmaxf(fmaf(2.0f, xc.y, -shift) * inv, -1.0f + EPS), 1.0f - EPS);
    cj.z = fminf(fmaxf(fmaf(2.0f, xc.z, -shift) * inv, -1.0f + EPS), 1.0f - EPS);
    cj.w = fminf(fmaxf(fmaf(2.0f, xc.w, -shift) * inv, -1.0f + EPS), 1.0f - EPS);
    sj.x = sqrtf(fmaxf(fmaf(-cj.x, cj.x, 1.0f), 0.0f));
    sj.y = sqrtf(fmaxf(fmaf(-cj.y, cj.y, 1.0f), 0.0f));
    sj.z = sqrtf(fmaxf(fmaf(-cj.z, cj.z, 1.0f), 0.0f));
    sj.w = sqrtf(fmaxf(fmaf(-cj.w, cj.w, 1.0f), 0.0f));

    const int row0 = chunk * ROWS_PER_CHUNK;
    float4* __restrict__ out4 =
        (float4*)(out + (size_t)b * N * N + (size_t)row0 * N);

    // 64 rows, 2 halves -> 32 rows per thread
    #pragma unroll 8
    for (int r = half; r < ROWS_PER_CHUNK; r += 2) {
        const float xr = __ldg(&xb[row0 + r]);    // broadcast, L1-hot
        float ci = fmaf(2.0f, xr, -shift) * inv;
        ci = fminf(fmaxf(ci, -1.0f + EPS), 1.0f - EPS);
        const float si = sqrtf(fmaxf(fmaf(-ci, ci, 1.0f), 0.0f));
        float4 rv;
        rv.x = fmaf(ci, cj.x, -si * sj.x);
        rv.y = fmaf(ci, cj.y, -si * sj.y);
        rv.z = fmaf(ci, cj.z, -si * sj.z);
        rv.w = fmaf(ci, cj.w, -si * sj.w);
        __stcs(&out4[r * 128 + col], rv);
    }
}

extern "C" void kernel_launch(void* const* d_in, const int* in_sizes, int n_in,
                              void* d_out, int out_size) {
    const float* x = (const float*)d_in[0];
    float* out = (float*)d_out;
    dim3 grid(B, CHUNKS);
    gram_kernel<<<grid, THREADS>>>(x, out);
}

// round 7
// speedup vs baseline: 1.0076x; 1.0056x over previous
#include <cuda_runtime.h>

// g[b,0,i,j] = cos(phi_i + phi_j) with phi = arccos(c)
//            = c_i*c_j - s_i*s_j,  s = sqrt(1 - c^2)
// c = clamp((2x - mx - mn)/(mx - mn), -1+eps, 1-eps) per batch row.
//
// Single kernel, zero barriers, zero smem. Warp-redundant min/max via
// shuffles; each lane precomputes ONE row's (ci,si); the store loop gets
// row values via __shfl_sync so its body is just 2 SHFL + 8 FMA + STG.128.

#define N 512
#define B 512
#define THREADS 256
#define CHUNKS 8                      // row-chunks per batch
#define ROWS_PER_CHUNK (N / CHUNKS)   // 64

__global__ __launch_bounds__(THREADS)
void gram_kernel(const float* __restrict__ x, float* __restrict__ out) {
    const int b = blockIdx.x;
    const int chunk = blockIdx.y;
    const int tid = threadIdx.x;
    const int lane = tid & 31;

    const float* __restrict__ xb = x + (size_t)b * N;
    const float4* __restrict__ xb4 = (const float4*)xb;

    // Warp-redundant min/max over all 512 floats: 4 lane-strided LDG.128.
    const float4 a0 = __ldg(&xb4[lane]);
    const float4 a1 = __ldg(&xb4[lane + 32]);
    const float4 a2 = __ldg(&xb4[lane + 64]);
    const float4 a3 = __ldg(&xb4[lane + 96]);

    float mn = fminf(fminf(fminf(a0.x, a0.y), fminf(a0.z, a0.w)),
                     fminf(fminf(a1.x, a1.y), fminf(a1.z, a1.w)));
    mn = fminf(mn, fminf(fminf(fminf(a2.x, a2.y), fminf(a2.z, a2.w)),
                         fminf(fminf(a3.x, a3.y), fminf(a3.z, a3.w))));
    float mx = fmaxf(fmaxf(fmaxf(a0.x, a0.y), fmaxf(a0.z, a0.w)),
                     fmaxf(fmaxf(a1.x, a1.y), fmaxf(a1.z, a1.w)));
    mx = fmaxf(mx, fmaxf(fmaxf(fmaxf(a2.x, a2.y), fmaxf(a2.z, a2.w)),
                         fmaxf(fmaxf(a3.x, a3.y), fmaxf(a3.z, a3.w))));
    #pragma unroll
    for (int o = 16; o > 0; o >>= 1) {
        mn = fminf(mn, __shfl_xor_sync(0xFFFFFFFFu, mn, o));
        mx = fmaxf(mx, __shfl_xor_sync(0xFFFFFFFFu, mx, o));
    }

    const float inv = 1.0f / (mx - mn);
    const float shift = mx + mn;
    const float EPS = 1e-6f;

    // This thread's 4 columns (L1-hot re-read)
    const int col  = tid & 127;          // float4 column group 0..127
    const int half = tid >> 7;           // row parity (uniform per warp)
    const float4 xc = __ldg(&xb4[col]);

    float4 cj, sj;
    cj.x = fminf(fmaxf(fmaf(2.0f, xc.x, -shift) * inv, -1.0f + EPS), 1.0f - EPS);
    cj.y = fminf(fmaxf(fmaf(2.0f, xc.y, -shift) * inv, -1.0f + EPS), 1.0f - EPS);
    cj.z = fminf(fmaxf(fmaf(2.0f, xc.z, -shift) * inv, -1.0f + EPS), 1.0f - EPS);
    cj.w = fminf(fmaxf(fmaf(2.0f, xc.w, -shift) * inv, -1.0f + EPS), 1.0f - EPS);
    sj.x = sqrtf(fmaxf(fmaf(-cj.x, cj.x, 1.0f), 0.0f));
    sj.y = sqrtf(fmaxf(fmaf(-cj.y, cj.y, 1.0f), 0.0f));
    sj.z = sqrtf(fmaxf(fmaf(-cj.z, cj.z, 1.0f), 0.0f));
    sj.w = sqrtf(fmaxf(fmaf(-cj.w, cj.w, 1.0f), 0.0f));

    // Per-lane row precompute: lane l owns row (half + 2*l) of this chunk.
    const int row0 = chunk * ROWS_PER_CHUNK;
    const float xr = __ldg(&xb[row0 + half + 2 * lane]);
    float cr = fminf(fmaxf(fmaf(2.0f, xr, -shift) * inv, -1.0f + EPS), 1.0f - EPS);
    float sr = sqrtf(fmaxf(fmaf(-cr, cr, 1.0f), 0.0f));

    float4* __restrict__ out4 =
        (float4*)(out + (size_t)b * N * N + (size_t)row0 * N);

    // 32 rows per thread; row (ci,si) broadcast from lane k via shuffle.
    #pragma unroll
    for (int k = 0; k < 32; k++) {
        const float ci = __shfl_sync(0xFFFFFFFFu, cr, k);
        const float si = __shfl_sync(0xFFFFFFFFu, sr, k);
        const int r = half + 2 * k;
        float4 rv;
        rv.x = fmaf(ci, cj.x, -si * sj.x);
        rv.y = fmaf(ci, cj.y, -si * sj.y);
        rv.z = fmaf(ci, cj.z, -si * sj.z);
        rv.w = fmaf(ci, cj.w, -si * sj.w);
        __stcs(&out4[r * 128 + col], rv);
    }
}

extern "C" void kernel_launch(void* const* d_in, const int* in_sizes, int n_in,
                              void* d_out, int out_size) {
    const float* x = (const float*)d_in[0];
    float* out = (float*)d_out;
    dim3 grid(B, CHUNKS);
    gram_kernel<<<grid, THREADS>>>(x, out);
}